// round 6
// baseline (speedup 1.0000x reference)
#include <cuda_runtime.h>
#include <cuda_bf16.h>
#include <math.h>

// Problem constants (fixed by setup_inputs)
#define BS    16
#define T     1024
#define DF    80          // feature dim
#define DF4   20          // as float4
#define SIZE  4096
#define TPB   256         // 8 warps
#define WARPS 8
#define RPW   4           // rows per warp (serial)
#define RPB   (WARPS*RPW) // 32 rows per block
#define FULLM 0xFFFFFFFFu

// Device scratch (allocation-free): sorted centers + permutation per batch
__device__ float g_cs[BS * T];
__device__ int   g_ci[BS * T];

// ---------------------------------------------------------------------------
// Kernel 1: fp32 cumsum replicating jax.lax.associative_scan's association
// tree, then centers, then bitonic sort by c (monotone for every batch,
// incl. batch 0 whose cumsum row is zeroed by the reference).
// ---------------------------------------------------------------------------
__global__ void prep_kernel(const float* __restrict__ d) {
    __shared__ float r[2047];
    __shared__ float s[2047];
    __shared__ float cv[T];
    __shared__ int   ci[T];
    const int b = blockIdx.x;
    const int t = threadIdx.x;

    const float v = d[b * T + t];
    r[t] = v;
    __syncthreads();

    {   // upsweep: pair sums
        int off = 0, n = T;
        while (n > 1) {
            int noff = off + n;
            if (t < (n >> 1))
                r[noff + t] = __fadd_rn(r[off + 2 * t], r[off + 2 * t + 1]);
            __syncthreads();
            off = noff; n >>= 1;
        }
    }
    if (t == 0) s[2046] = r[2046];
    __syncthreads();
    #pragma unroll
    for (int L = 9; L >= 0; --L) {   // downsweep
        const int n    = T >> L;
        const int off  = 2048 - (2048 >> L);
        const int offn = 2048 - (2048 >> (L + 1));
        if (t < n) {
            float val;
            if (t == 0)        val = r[off];
            else if (t & 1)    val = s[offn + (t >> 1)];
            else               val = __fadd_rn(s[offn + (t >> 1) - 1], r[off + t]);
            s[off + t] = val;
        }
        __syncthreads();
    }

    float cs;
    if (b == 0)       cs = 0.0f;         // reference zeroes whole batch-0 row
    else if (t == 0)  cs = s[T - 1];     // rolled: total sum
    else              cs = s[t - 1];     // exclusive prefix
    cv[t] = __fadd_rn(0.5f * v, cs);
    ci[t] = t;
    __syncthreads();

    for (int k = 2; k <= T; k <<= 1) {   // bitonic sort ascending by cv
        for (int j = k >> 1; j > 0; j >>= 1) {
            int i = t ^ j;
            if (i > t) {
                bool up = ((t & k) == 0);
                float a = cv[t], bb = cv[i];
                if ((a > bb) == up) {
                    cv[t] = bb; cv[i] = a;
                    int tmp = ci[t]; ci[t] = ci[i]; ci[i] = tmp;
                }
            }
            __syncthreads();
        }
    }
    g_cs[b * T + t] = cv[t];
    g_ci[b * T + t] = ci[t];
}

// ---------------------------------------------------------------------------
// Row processor: one warp, RPW rows, quantization-faithful scoring.
// POW2: two_s2 is a power of two -> fmul by exact reciprocal == fdiv (bitwise).
// ---------------------------------------------------------------------------
template<bool POW2>
__device__ __forceinline__ void process_rows(
    const float* __restrict__ c_sh, const int* __restrict__ i_sh,
    const float4* __restrict__ h4, float* __restrict__ out,
    int b, int s_base, int lane, float two_s2, float inv2s2)
{
    // ---- phase 1: binary search of tval for each of RPW rows (one per lane)
    int rq = (lane < RPW) ? lane : 0;
    float tq = (float)(s_base + rq) + 1.5f;
    int lo = 0, hi = T;
    #pragma unroll
    for (int it = 0; it < 10; ++it) {
        int m = (lo + hi) >> 1;
        if (c_sh[m] > tq) hi = m; else lo = m + 1;
    }
    int kc = lo;
    // per-lane (rows 0..RPW-1): max score + window radius, reference-rounded
    int kA = kc < (T - 1) ? kc : (T - 1);
    int kB = (kc - 1) > 0 ? (kc - 1) : 0;
    float dA  = __fsub_rn(tq, c_sh[kA]);
    float dB  = __fsub_rn(tq, c_sh[kB]);
    float sqA = __fmul_rn(dA, dA);
    float sqB = __fmul_rn(dB, dB);
    float sqmin = fminf(sqA, sqB);
    float smax_l = POW2 ? -__fmul_rn(sqmin, inv2s2) : -__fdiv_rn(sqmin, two_s2);
    float rr_l   = sqrtf(sqmin + 24.0f * two_s2);

    // ---- phase 2: search window edges, 2 queries per row (lanes 0..2*RPW-1)
    int   r2   = (lane >> 1) & (RPW - 1);
    float tv2  = (float)(s_base + r2) + 1.5f;
    float rr2  = __shfl_sync(FULLM, rr_l, r2);
    float q    = (lane & 1) ? (tv2 + rr2) : (tv2 - rr2);
    lo = 0; hi = T;
    #pragma unroll
    for (int it = 0; it < 10; ++it) {
        int m = (lo + hi) >> 1;
        if (c_sh[m] > q) hi = m; else lo = m + 1;
    }
    int edge = lo;

    const int    col  = lane < DF4 ? lane : (DF4 - 1);
    const size_t bOff = (size_t)b * T;

    // ---- per-row main loops
    #pragma unroll
    for (int r = 0; r < RPW; ++r) {
        const int   klo  = __shfl_sync(FULLM, edge, 2 * r);
        const int   khi  = __shfl_sync(FULLM, edge, 2 * r + 1) - 1;
        const float smax = __shfl_sync(FULLM, smax_l, r);
        const float tval = (float)(s_base + r) + 1.5f;

        float  l = 0.0f;
        float4 acc = make_float4(0.f, 0.f, 0.f, 0.f);

        for (int k0 = klo; k0 <= khi; k0 += 32) {
            // each lane: faithful weight for k0+lane
            const int kk = k0 + lane;
            float cc = c_sh[kk];                       // padded to T+32
            float dt = __fsub_rn(tval, cc);
            float sq = __fmul_rn(dt, dt);
            float sc = POW2 ? -__fmul_rn(sq, inv2s2) : -__fdiv_rn(sq, two_s2);
            float e  = __fsub_rn(sc, smax);
            float w  = __expf(e);
            if (kk > khi) w = 0.0f;
            l += w;

            const int nk = (khi - k0 + 1) < 32 ? (khi - k0 + 1) : 32;
            #pragma unroll 4
            for (int m = 0; m < nk; ++m) {
                float wm = __shfl_sync(FULLM, w, m);   // uniform src lane
                int   id = i_sh[k0 + m];               // LDS broadcast
                float4 v = h4[(bOff + id) * DF4 + col];
                acc.x += wm * v.x; acc.y += wm * v.y;
                acc.z += wm * v.z; acc.w += wm * v.w;
            }
        }

        // reduce denominator over the warp
        #pragma unroll
        for (int o = 16; o; o >>= 1) l += __shfl_xor_sync(FULLM, l, o);
        const float linv = 1.0f / l;

        if (lane < DF4) {
            float4 v;
            v.x = acc.x * linv; v.y = acc.y * linv;
            v.z = acc.z * linv; v.w = acc.w * linv;
            ((float4*)out)[((size_t)b * SIZE + s_base + r) * DF4 + lane] = v;
        }
    }
}

// ---------------------------------------------------------------------------
// Kernel 2: warp-per-row windowed softmax over SORTED centers.
// ---------------------------------------------------------------------------
__global__ void __launch_bounds__(TPB) alignment_kernel(
    const float* __restrict__ h,      // [BS, T, DF]
    const float* __restrict__ sigma,  // [1]
    float* __restrict__ out)          // [BS, SIZE, DF]
{
    __shared__ float c_sh[T + 32];
    __shared__ int   i_sh[T + 32];
    const int b    = blockIdx.y;
    const int tid  = threadIdx.x;
    const int lane = tid & 31;
    const int wid  = tid >> 5;

    for (int i = tid; i < T; i += TPB) {
        c_sh[i] = g_cs[b * T + i];
        i_sh[i] = g_ci[b * T + i];
    }
    if (tid < 32) { c_sh[T + tid] = INFINITY; i_sh[T + tid] = 0; }
    __syncthreads();

    const float sg     = sigma[0];
    const float two_s2 = 2.0f * sg * sg;
    const unsigned tb  = __float_as_uint(two_s2);
    const bool pow2    = ((tb & 0x007FFFFFu) == 0u) && (two_s2 > 0.0f);
    const float inv2s2 = 1.0f / two_s2;   // exact when pow2

    const int s_base = blockIdx.x * RPB + wid * RPW;
    const float4* h4 = (const float4*)h;

    if (pow2) process_rows<true >(c_sh, i_sh, h4, out, b, s_base, lane, two_s2, inv2s2);
    else      process_rows<false>(c_sh, i_sh, h4, out, b, s_base, lane, two_s2, inv2s2);
}

// ---------------------------------------------------------------------------
extern "C" void kernel_launch(void* const* d_in, const int* in_sizes, int n_in,
                              void* d_out, int out_size) {
    const float* h     = (const float*)d_in[0];  // [16,1024,80]
    const float* d     = (const float*)d_in[1];  // [16,1024]
    const float* sigma = (const float*)d_in[2];  // [1]

    prep_kernel<<<BS, T>>>(d);
    dim3 grid(SIZE / RPB, BS);
    alignment_kernel<<<grid, TPB>>>(h, sigma, (float*)d_out);
}

// round 7
// speedup vs baseline: 3.2292x; 3.2292x over previous
#include <cuda_runtime.h>
#include <cuda_bf16.h>
#include <math.h>

// Problem constants (fixed by setup_inputs)
#define BS    16
#define T     1024
#define DF    80          // feature dim
#define DF4   20          // as float4
#define SIZE  4096
#define TPB   256         // 4 lanes per row -> 64 rows per block
#define RPB   64          // rows per block
#define TPAD  4           // padding entries (+inf centers) for chunk-of-4 loop
#define FULLM 0xFFFFFFFFu

// Device scratch (allocation-free): sorted centers + permutation per batch
__device__ float g_cs[BS * T];
__device__ int   g_ci[BS * T];

// ---------------------------------------------------------------------------
// Kernel 1: fp32 cumsum replicating jax.lax.associative_scan's association
// tree, then centers, then bitonic sort by c (monotone for every batch,
// incl. batch 0 whose cumsum row is zeroed by the reference).
// ---------------------------------------------------------------------------
__global__ void prep_kernel(const float* __restrict__ d) {
    __shared__ float r[2047];
    __shared__ float s[2047];
    __shared__ float cv[T];
    __shared__ int   ci[T];
    const int b = blockIdx.x;
    const int t = threadIdx.x;

    const float v = d[b * T + t];
    r[t] = v;
    __syncthreads();

    {   // upsweep: pair sums
        int off = 0, n = T;
        while (n > 1) {
            int noff = off + n;
            if (t < (n >> 1))
                r[noff + t] = __fadd_rn(r[off + 2 * t], r[off + 2 * t + 1]);
            __syncthreads();
            off = noff; n >>= 1;
        }
    }
    if (t == 0) s[2046] = r[2046];
    __syncthreads();
    #pragma unroll
    for (int L = 9; L >= 0; --L) {   // downsweep
        const int n    = T >> L;
        const int off  = 2048 - (2048 >> L);
        const int offn = 2048 - (2048 >> (L + 1));
        if (t < n) {
            float val;
            if (t == 0)        val = r[off];
            else if (t & 1)    val = s[offn + (t >> 1)];
            else               val = __fadd_rn(s[offn + (t >> 1) - 1], r[off + t]);
            s[off + t] = val;
        }
        __syncthreads();
    }

    float cs;
    if (b == 0)       cs = 0.0f;         // reference zeroes whole batch-0 row
    else if (t == 0)  cs = s[T - 1];     // rolled: total sum
    else              cs = s[t - 1];     // exclusive prefix
    cv[t] = __fadd_rn(0.5f * v, cs);
    ci[t] = t;
    __syncthreads();

    for (int k = 2; k <= T; k <<= 1) {   // bitonic sort ascending by cv
        for (int j = k >> 1; j > 0; j >>= 1) {
            int i = t ^ j;
            if (i > t) {
                bool up = ((t & k) == 0);
                float a = cv[t], bb = cv[i];
                if ((a > bb) == up) {
                    cv[t] = bb; cv[i] = a;
                    int tmp = ci[t]; ci[t] = ci[i]; ci[i] = tmp;
                }
            }
            __syncthreads();
        }
    }
    g_cs[b * T + t] = cv[t];
    g_ci[b * T + t] = ci[t];
}

// ---------------------------------------------------------------------------
// Main body (R5 structure): quad per row, 8 rows per warp, warp-union window,
// quantization-faithful scoring:
//   dt = fsub(t,c); sq = fmul(dt,dt); sc = -fdiv(sq,2s^2); e = fsub(sc,max)
// POW2: 2*sigma^2 is a power of two -> fmul by exact reciprocal == fdiv.
// ---------------------------------------------------------------------------
template<bool POW2>
__device__ __forceinline__ void run_rows(
    const float* __restrict__ c_sh, const int* __restrict__ i_sh,
    const float4* __restrict__ h4, float* __restrict__ out,
    int b, int s, int f, float two_s2, float inv2s2)
{
    const float tval = (float)s + 1.5f;

    // first index in [0,T) with c_sh[k] > x (T if none) — c_sh sorted
    auto lower = [&](float x) -> int {
        int lo = 0, hi = T;
        while (lo < hi) {
            int m = (lo + hi) >> 1;
            if (c_sh[m] > x) hi = m; else lo = m + 1;
        }
        return lo;
    };

    // exact global max score (reference-rounded squares)
    int kc = lower(tval);
    int kA = kc < (T - 1) ? kc : (T - 1);
    int kB = (kc - 1) > 0 ? (kc - 1) : 0;
    float dA  = __fsub_rn(tval, c_sh[kA]);
    float dB  = __fsub_rn(tval, c_sh[kB]);
    float sqA = __fmul_rn(dA, dA);
    float sqB = __fmul_rn(dB, dB);
    float sqmin = fminf(sqA, sqB);
    const float score_max = POW2 ? -__fmul_rn(sqmin, inv2s2)
                                 : -__fdiv_rn(sqmin, two_s2);

    // window: e > -24
    const float rr  = sqrtf(sqmin + 24.0f * two_s2);
    int klo = lower(tval - rr);
    int khi = lower(tval + rr) - 1;

    // union over the warp's 8 consecutive rows (keeps all lanes convergent)
    int wlo = __reduce_min_sync(FULLM, klo);
    int whi = __reduce_max_sync(FULLM, khi);

    const size_t bOff = (size_t)b * T;

    float  l = 0.0f;
    float4 acc[5];
    #pragma unroll
    for (int j = 0; j < 5; ++j) acc[j] = make_float4(0.f, 0.f, 0.f, 0.f);

    // chunk of 4 k's: lane f computes the faithful weight for k0+f (own row),
    // quad-shuffles, then each lane accumulates its 5 float4 columns.
    for (int k0 = wlo; k0 <= whi; k0 += 4) {
        float dt = __fsub_rn(tval, c_sh[k0 + f]);
        float sq = __fmul_rn(dt, dt);
        float sc = POW2 ? -__fmul_rn(sq, inv2s2) : -__fdiv_rn(sq, two_s2);
        float e  = __fsub_rn(sc, score_max);
        float w0 = __expf(e);                           // k = k0 + f
        float w1 = __shfl_xor_sync(FULLM, w0, 1);       // k = k0 + (f^1)
        float w2 = __shfl_xor_sync(FULLM, w0, 2);       // k = k0 + (f^2)
        float w3 = __shfl_xor_sync(FULLM, w1, 2);       // k = k0 + (f^3)

        int i0 = i_sh[k0 + f];
        int i1 = i_sh[k0 + (f ^ 1)];
        int i2 = i_sh[k0 + (f ^ 2)];
        int i3 = i_sh[k0 + (f ^ 3)];

        l += ((w0 + w1) + (w2 + w3));

        const float4* r0 = h4 + (bOff + i0) * DF4 + f;
        const float4* r1 = h4 + (bOff + i1) * DF4 + f;
        const float4* r2 = h4 + (bOff + i2) * DF4 + f;
        const float4* r3 = h4 + (bOff + i3) * DF4 + f;
        #pragma unroll
        for (int j = 0; j < 5; ++j) {
            float4 v0 = r0[4 * j];
            acc[j].x += w0 * v0.x; acc[j].y += w0 * v0.y;
            acc[j].z += w0 * v0.z; acc[j].w += w0 * v0.w;
            float4 v1 = r1[4 * j];
            acc[j].x += w1 * v1.x; acc[j].y += w1 * v1.y;
            acc[j].z += w1 * v1.z; acc[j].w += w1 * v1.w;
            float4 v2 = r2[4 * j];
            acc[j].x += w2 * v2.x; acc[j].y += w2 * v2.y;
            acc[j].z += w2 * v2.z; acc[j].w += w2 * v2.w;
            float4 v3 = r3[4 * j];
            acc[j].x += w3 * v3.x; acc[j].y += w3 * v3.y;
            acc[j].z += w3 * v3.z; acc[j].w += w3 * v3.w;
        }
    }

    const float linv = 1.0f / l;
    float4* o = (float4*)out + ((size_t)b * SIZE + s) * DF4 + f;
    #pragma unroll
    for (int j = 0; j < 5; ++j) {
        float4 v;
        v.x = acc[j].x * linv; v.y = acc[j].y * linv;
        v.z = acc[j].z * linv; v.w = acc[j].w * linv;
        o[4 * j] = v;
    }
}

// ---------------------------------------------------------------------------
// Kernel 2: load-balanced row mapping. Warp i of block x handles the 8
// consecutive rows starting at 8*(i*64 + x): every block gets one warp-group
// from each s-octile, so heavy low-s windows spread evenly across blocks.
// ---------------------------------------------------------------------------
__global__ void __launch_bounds__(TPB) alignment_kernel(
    const float* __restrict__ h,      // [BS, T, DF]
    const float* __restrict__ sigma,  // [1]
    float* __restrict__ out)          // [BS, SIZE, DF]
{
    __shared__ float c_sh[T + TPAD];
    __shared__ int   i_sh[T + TPAD];
    const int b    = blockIdx.y;
    const int tid  = threadIdx.x;
    const int f    = tid & 3;               // lane-in-quad = feature group
    const int wrp  = tid >> 5;              // warp in block (0..7)
    const int quad = (tid & 31) >> 2;       // row-in-warp  (0..7)
    // balanced mapping: s = 512*warp + 8*block_x + quad
    const int s    = 512 * wrp + 8 * blockIdx.x + quad;

    for (int i = tid; i < T; i += TPB) {
        c_sh[i] = g_cs[b * T + i];
        i_sh[i] = g_ci[b * T + i];
    }
    if (tid < TPAD) { c_sh[T + tid] = INFINITY; i_sh[T + tid] = 0; }
    __syncthreads();

    const float sg     = sigma[0];
    const float two_s2 = 2.0f * sg * sg;
    const unsigned tb  = __float_as_uint(two_s2);
    const bool pow2    = ((tb & 0x007FFFFFu) == 0u) && (two_s2 > 0.0f);
    const float inv2s2 = 1.0f / two_s2;     // exact when pow2

    const float4* h4 = (const float4*)h;
    if (pow2) run_rows<true >(c_sh, i_sh, h4, out, b, s, f, two_s2, inv2s2);
    else      run_rows<false>(c_sh, i_sh, h4, out, b, s, f, two_s2, inv2s2);
}

// ---------------------------------------------------------------------------
extern "C" void kernel_launch(void* const* d_in, const int* in_sizes, int n_in,
                              void* d_out, int out_size) {
    const float* h     = (const float*)d_in[0];  // [16,1024,80]
    const float* d     = (const float*)d_in[1];  // [16,1024]
    const float* sigma = (const float*)d_in[2];  // [1]

    prep_kernel<<<BS, T>>>(d);
    dim3 grid(SIZE / RPB, BS);                   // 64 x 16
    alignment_kernel<<<grid, TPB>>>(h, sigma, (float*)d_out);
}